// round 1
// baseline (speedup 1.0000x reference)
#include <cuda_runtime.h>
#include <math.h>

// Problem constants
#define Bb   2
#define Nn   1024
#define Cc   1024
#define Hh   16
#define Dd   64
#define BLKc 8
#define NBc  128
#define TOPKc 7
#define BHc  (Bb*Hh)          // 32
#define NCHUNK 8              // kv accumulation chunks
#define CHLEN (Nn/NCHUNK)     // 128

// ---------------- scratch (device globals; no allocation) ----------------
__device__ __align__(16) float g_qkv [Bb*Nn*3*Cc];        // (B,N,3C)
__device__ __align__(16) float g_q   [BHc*Nn*Dd];
__device__ __align__(16) float g_k   [BHc*Nn*Dd];
__device__ __align__(16) float g_v   [BHc*Nn*Dd];
__device__ __align__(16) float g_pq  [BHc*Nn*Dd];         // phi_q
__device__ __align__(16) float g_pk  [BHc*Nn*Dd];         // phi_k
__device__ __align__(16) float g_kcmp[BHc*NBc*Dd];
__device__               int   g_topk[BHc*Nn*TOPKc];
__device__ __align__(16) float g_kvp [NCHUNK*BHc*Dd*Dd];  // partial kv
__device__ __align__(16) float g_zp  [NCHUNK*BHc*Dd];     // partial z
__device__ __align__(16) float g_kv  [BHc*Dd*Dd];
__device__ __align__(16) float g_z   [BHc*Dd];
__device__ __align__(16) float g_attn[Bb*Nn*Cc];          // (B,N,C) pre-proj

// ---------------- generic fp32 GEMM: C = A(MxK) @ B(KxN) + bias ----------
// BM=128 BN=64 BK=16, 256 threads, 8x4 microtile.
__global__ __launch_bounds__(256) void gemm_bias_kernel(
    const float* __restrict__ A, const float* __restrict__ B,
    const float* __restrict__ bias, float* __restrict__ C,
    int M, int N, int K)
{
    __shared__ float As[16][128 + 4];
    __shared__ float Bs[16][64];
    int tid = threadIdx.x;
    int tx = tid & 15;        // 16 col groups * 4 = 64 cols
    int ty = tid >> 4;        // 16 row groups * 8 = 128 rows
    int bm = blockIdx.y * 128;
    int bn = blockIdx.x * 64;

    float acc[8][4];
#pragma unroll
    for (int i = 0; i < 8; i++)
#pragma unroll
        for (int j = 0; j < 4; j++) acc[i][j] = 0.f;

    for (int k0 = 0; k0 < K; k0 += 16) {
        // load A tile (128x16) : 512 float4, 2 per thread
#pragma unroll
        for (int u = 0; u < 2; u++) {
            int f4 = tid * 2 + u;
            int r  = f4 >> 2;
            int kq = f4 & 3;
            float4 av = *reinterpret_cast<const float4*>(
                A + (size_t)(bm + r) * K + k0 + kq * 4);
            As[kq*4+0][r] = av.x; As[kq*4+1][r] = av.y;
            As[kq*4+2][r] = av.z; As[kq*4+3][r] = av.w;
        }
        // load B tile (16x64) : 256 float4, 1 per thread
        {
            int kk = tid >> 4;
            int nc = tid & 15;
            float4 bv = *reinterpret_cast<const float4*>(
                B + (size_t)(k0 + kk) * N + bn + nc * 4);
            *reinterpret_cast<float4*>(&Bs[kk][nc*4]) = bv;
        }
        __syncthreads();
#pragma unroll
        for (int kk = 0; kk < 16; kk++) {
            float a[8], b[4];
#pragma unroll
            for (int i = 0; i < 8; i++) a[i] = As[kk][ty*8 + i];
#pragma unroll
            for (int j = 0; j < 4; j++) b[j] = Bs[kk][tx*4 + j];
#pragma unroll
            for (int i = 0; i < 8; i++)
#pragma unroll
                for (int j = 0; j < 4; j++) acc[i][j] += a[i] * b[j];
        }
        __syncthreads();
    }
#pragma unroll
    for (int i = 0; i < 8; i++) {
        int r = bm + ty*8 + i;
#pragma unroll
        for (int j = 0; j < 4; j++) {
            int c = bn + tx*4 + j;
            C[(size_t)r * N + c] = acc[i][j] + bias[c];
        }
    }
}

// ------------- LayerNorm(q,k) + phi softmax + v copy, per (b,n) ----------
// grid = B*N blocks, 512 threads = 16 warps; warp h handles head h.
__global__ __launch_bounds__(512) void ln_phi_kernel(
    const float* __restrict__ qw, const float* __restrict__ qb,
    const float* __restrict__ kw, const float* __restrict__ kb)
{
    int bn = blockIdx.x;
    int b = bn / Nn, n = bn % Nn;
    int h = threadIdx.x >> 5;
    int lane = threadIdx.x & 31;
    const float* row = g_qkv + (size_t)bn * (3*Cc);
    int d0 = lane, d1 = lane + 32;
    size_t obase = ((size_t)(b*Hh + h) * Nn + n) * Dd;

    // ---- q ----
    {
        float v0 = row[h*Dd + d0], v1 = row[h*Dd + d1];
        float s = v0 + v1;
#pragma unroll
        for (int o = 16; o; o >>= 1) s += __shfl_xor_sync(~0u, s, o);
        float m = s * (1.f/64.f);
        float a0 = v0 - m, a1 = v1 - m;
        float vs = a0*a0 + a1*a1;
#pragma unroll
        for (int o = 16; o; o >>= 1) vs += __shfl_xor_sync(~0u, vs, o);
        float r = rsqrtf(vs * (1.f/64.f) + 1e-6f);
        float y0 = a0*r*qw[d0] + qb[d0];
        float y1 = a1*r*qw[d1] + qb[d1];
        g_q[obase + d0] = y0; g_q[obase + d1] = y1;
        float mx = fmaxf(y0, y1);
#pragma unroll
        for (int o = 16; o; o >>= 1) mx = fmaxf(mx, __shfl_xor_sync(~0u, mx, o));
        float e0 = __expf(y0 - mx), e1 = __expf(y1 - mx);
        float se = e0 + e1;
#pragma unroll
        for (int o = 16; o; o >>= 1) se += __shfl_xor_sync(~0u, se, o);
        float inv = 1.f / se;
        g_pq[obase + d0] = e0*inv; g_pq[obase + d1] = e1*inv;
    }
    // ---- k ----
    {
        float v0 = row[Cc + h*Dd + d0], v1 = row[Cc + h*Dd + d1];
        float s = v0 + v1;
#pragma unroll
        for (int o = 16; o; o >>= 1) s += __shfl_xor_sync(~0u, s, o);
        float m = s * (1.f/64.f);
        float a0 = v0 - m, a1 = v1 - m;
        float vs = a0*a0 + a1*a1;
#pragma unroll
        for (int o = 16; o; o >>= 1) vs += __shfl_xor_sync(~0u, vs, o);
        float r = rsqrtf(vs * (1.f/64.f) + 1e-6f);
        float y0 = a0*r*kw[d0] + kb[d0];
        float y1 = a1*r*kw[d1] + kb[d1];
        g_k[obase + d0] = y0; g_k[obase + d1] = y1;
        float mx = fmaxf(y0, y1);
#pragma unroll
        for (int o = 16; o; o >>= 1) mx = fmaxf(mx, __shfl_xor_sync(~0u, mx, o));
        float e0 = __expf(y0 - mx), e1 = __expf(y1 - mx);
        float se = e0 + e1;
#pragma unroll
        for (int o = 16; o; o >>= 1) se += __shfl_xor_sync(~0u, se, o);
        float inv = 1.f / se;
        g_pk[obase + d0] = e0*inv; g_pk[obase + d1] = e1*inv;
    }
    // ---- v copy ----
    g_v[obase + d0] = row[2*Cc + h*Dd + d0];
    g_v[obase + d1] = row[2*Cc + h*Dd + d1];
}

// ------------- compressed keys: mean pool over BLK=8 ---------------------
__global__ __launch_bounds__(64) void kcmp_kernel()
{
    int bhm = blockIdx.x;            // B*H*NB
    int d = threadIdx.x;
    int bh = bhm / NBc, m = bhm % NBc;
    const float* kr = g_k + ((size_t)bh*Nn + m*BLKc) * Dd;
    float s = 0.f;
#pragma unroll
    for (int t = 0; t < BLKc; t++) s += kr[t*Dd + d];
    g_kcmp[(size_t)bhm*Dd + d] = s * (1.f/BLKc);
}

// ------------- kv/z partials (deterministic, no atomics) -----------------
// grid (BH, NCHUNK), 256 threads. thread: e = tid&63, d-group = tid>>6 (16 d's).
__global__ __launch_bounds__(256) void kv_chunk_kernel()
{
    int bh = blockIdx.x;
    int ch = blockIdx.y;
    int tid = threadIdx.x;
    int e = tid & 63;
    int dg = tid >> 6;               // 0..3
    __shared__ float sh[128];
    float acc[16];
#pragma unroll
    for (int j = 0; j < 16; j++) acc[j] = 0.f;
    float zacc = 0.f;
    size_t base = (size_t)bh * Nn * Dd;
    for (int i = 0; i < CHLEN; i++) {
        int n = ch * CHLEN + i;
        __syncthreads();
        if (tid < 128)
            sh[tid] = (tid < 64) ? g_pk[base + (size_t)n*Dd + tid]
                                 : g_v [base + (size_t)n*Dd + tid - 64];
        __syncthreads();
        float ve = sh[64 + e];
#pragma unroll
        for (int j = 0; j < 16; j++) acc[j] += sh[dg*16 + j] * ve;
        if (tid < 64) zacc += sh[tid];
    }
    float* out = g_kvp + ((size_t)ch * BHc + bh) * (Dd*Dd);
#pragma unroll
    for (int j = 0; j < 16; j++) out[(dg*16 + j)*Dd + e] = acc[j];
    if (tid < 64) g_zp[((size_t)ch * BHc + bh) * Dd + tid] = zacc;
}

__global__ __launch_bounds__(256) void kv_reduce_kernel()
{
    int idx = blockIdx.x * 256 + threadIdx.x;
    const int KVN = BHc*Dd*Dd;       // 131072
    const int ZN  = BHc*Dd;          // 2048
    if (idx < KVN) {
        float s = 0.f;
#pragma unroll
        for (int c = 0; c < NCHUNK; c++) s += g_kvp[(size_t)c*KVN + idx];
        g_kv[idx] = s;
    } else if (idx < KVN + ZN) {
        int z = idx - KVN;
        float s = 0.f;
#pragma unroll
        for (int c = 0; c < NCHUNK; c++) s += g_zp[(size_t)c*ZN + z];
        g_z[z] = s;
    }
}

// ------------- router + top-7 : warp per query ---------------------------
// grid = BH * (N/8), 256 threads = 8 warps, warp w -> query n0+w.
__global__ __launch_bounds__(256) void router_topk_kernel()
{
    int bh = blockIdx.x / (Nn/8);
    int n0 = (blockIdx.x % (Nn/8)) * 8;
    int warp = threadIdx.x >> 5;
    int lane = threadIdx.x & 31;
    int n = n0 + warp;
    __shared__ float sq[8][64];
    const float* qrow = g_q + ((size_t)bh*Nn + n) * Dd;
    sq[warp][lane]      = qrow[lane];
    sq[warp][lane + 32] = qrow[lane + 32];
    __syncwarp();
    const float scale = 0.125f;      // D^-0.5
    const float* kc = g_kcmp + (size_t)bh * NBc * Dd;
    float s0, s1, s2, s3;
    {
        float a0=0.f, a1=0.f, a2=0.f, a3=0.f;
        const float* r0 = kc + (lane*4 + 0) * Dd;
        const float* r1 = kc + (lane*4 + 1) * Dd;
        const float* r2 = kc + (lane*4 + 2) * Dd;
        const float* r3 = kc + (lane*4 + 3) * Dd;
#pragma unroll
        for (int d = 0; d < 64; d++) {
            float qd = sq[warp][d];
            a0 += qd * __ldg(r0 + d);
            a1 += qd * __ldg(r1 + d);
            a2 += qd * __ldg(r2 + d);
            a3 += qd * __ldg(r3 + d);
        }
        s0 = a0*scale; s1 = a1*scale; s2 = a2*scale; s3 = a3*scale;
    }
    int qidx = bh * Nn + n;
    const float NEGINF = -__int_as_float(0x7f800000);
#pragma unroll
    for (int r = 0; r < TOPKc; r++) {
        float bv = s0; int bj = 0;
        if (s1 > bv) { bv = s1; bj = 1; }
        if (s2 > bv) { bv = s2; bj = 2; }
        if (s3 > bv) { bv = s3; bj = 3; }
        int bm = lane*4 + bj;
#pragma unroll
        for (int o = 16; o; o >>= 1) {
            float ov = __shfl_xor_sync(~0u, bv, o);
            int   om = __shfl_xor_sync(~0u, bm, o);
            if (ov > bv || (ov == bv && om < bm)) { bv = ov; bm = om; }
        }
        if ((bm >> 2) == lane) {
            int j = bm & 3;
            if      (j == 0) s0 = NEGINF;
            else if (j == 1) s1 = NEGINF;
            else if (j == 2) s2 = NEGINF;
            else             s3 = NEGINF;
        }
        if (lane == 0) g_topk[(size_t)qidx*TOPKc + r] = bm;
    }
}

// ------------- fused sparse softmax attention + linear branch ------------
// grid = BH * (N/8), 256 threads = 8 warps, warp per query.
__global__ __launch_bounds__(256) void attn_kernel()
{
    int bh = blockIdx.x / (Nn/8);
    int b = bh / Hh, h = bh % Hh;
    int n0 = (blockIdx.x % (Nn/8)) * 8;
    int warp = threadIdx.x >> 5;
    int lane = threadIdx.x & 31;
    int n = n0 + warp;
    __shared__ float sq [8][64];
    __shared__ float spq[8][64];
    __shared__ float sp [8][64];
    __shared__ int   sblk[8][8];

    size_t qb = ((size_t)bh*Nn + n) * Dd;
    sq [warp][lane]      = g_q [qb + lane];
    sq [warp][lane + 32] = g_q [qb + lane + 32];
    spq[warp][lane]      = g_pq[qb + lane];
    spq[warp][lane + 32] = g_pq[qb + lane + 32];
    if (lane < TOPKc) sblk[warp][lane] = g_topk[((size_t)bh*Nn + n)*TOPKc + lane];
    __syncwarp();

    const float scale = 0.125f;
    const int NSEL = TOPKc * BLKc;   // 56
    const float NEGINF = -__int_as_float(0x7f800000);

    // logits for slots lane and lane+32
    float l0, l1;
    {
        int s = lane;                // always < 56
        int tok = sblk[warp][s >> 3] * BLKc + (s & 7);
        const float* kr = g_k + ((size_t)bh*Nn + tok) * Dd;
        float a = 0.f;
#pragma unroll
        for (int d = 0; d < 64; d++) a += sq[warp][d] * __ldg(kr + d);
        l0 = a * scale;
    }
    {
        int s = lane + 32;
        if (s < NSEL) {
            int tok = sblk[warp][s >> 3] * BLKc + (s & 7);
            const float* kr = g_k + ((size_t)bh*Nn + tok) * Dd;
            float a = 0.f;
#pragma unroll
            for (int d = 0; d < 64; d++) a += sq[warp][d] * __ldg(kr + d);
            l1 = a * scale;
        } else l1 = NEGINF;
    }
    float mx = fmaxf(l0, l1);
#pragma unroll
    for (int o = 16; o; o >>= 1) mx = fmaxf(mx, __shfl_xor_sync(~0u, mx, o));
    float e0 = __expf(l0 - mx);
    float e1 = (lane + 32 < NSEL) ? __expf(l1 - mx) : 0.f;
    float se = e0 + e1;
#pragma unroll
    for (int o = 16; o; o >>= 1) se += __shfl_xor_sync(~0u, se, o);
    float inv = 1.f / se;
    sp[warp][lane]      = e0 * inv;
    sp[warp][lane + 32] = e1 * inv;
    __syncwarp();

    // sparse output: lane owns dims d0=lane, d1=lane+32
    int d0 = lane, d1 = lane + 32;
    float a0 = 0.f, a1 = 0.f;
#pragma unroll
    for (int s = 0; s < NSEL; s++) {
        int tok = sblk[warp][s >> 3] * BLKc + (s & 7);
        const float* vr = g_v + ((size_t)bh*Nn + tok) * Dd;
        float p = sp[warp][s];
        a0 += p * vr[d0];
        a1 += p * vr[d1];
    }

    // linear branch
    const float* zr = g_z + (size_t)bh * Dd;
    float t = spq[warp][d0]*zr[d0] + spq[warp][d1]*zr[d1];
#pragma unroll
    for (int o = 16; o; o >>= 1) t += __shfl_xor_sync(~0u, t, o);
    float inv_den = 1.f / (t + 1e-6f);
    const float* kvm = g_kv + (size_t)bh * Dd * Dd;
    float n0a = 0.f, n1a = 0.f;
#pragma unroll
    for (int e = 0; e < 64; e++) {
        float pe = spq[warp][e];
        n0a += pe * kvm[e*Dd + d0];
        n1a += pe * kvm[e*Dd + d1];
    }
    size_t ob = ((size_t)(b*Nn + n)) * Cc + h*Dd;
    g_attn[ob + d0] = a0 + n0a * inv_den;
    g_attn[ob + d1] = a1 + n1a * inv_den;
}

// ---------------------------------------------------------------------------
extern "C" void kernel_launch(void* const* d_in, const int* in_sizes, int n_in,
                              void* d_out, int out_size)
{
    const float* x      = (const float*)d_in[0];
    const float* w_qkv  = (const float*)d_in[1];
    const float* b_qkv  = (const float*)d_in[2];
    const float* qw     = (const float*)d_in[3];
    const float* qb     = (const float*)d_in[4];
    const float* kw     = (const float*)d_in[5];
    const float* kb     = (const float*)d_in[6];
    const float* w_proj = (const float*)d_in[7];
    const float* b_proj = (const float*)d_in[8];
    float* out = (float*)d_out;

    void *p_qkv = nullptr, *p_attn = nullptr;
    cudaGetSymbolAddress(&p_qkv,  g_qkv);
    cudaGetSymbolAddress(&p_attn, g_attn);

    // 1) qkv = x @ w_qkv + b_qkv      (2048 x 1024 x 3072)
    {
        dim3 grid(3*Cc/64, Bb*Nn/128);
        gemm_bias_kernel<<<grid, 256>>>(x, w_qkv, b_qkv, (float*)p_qkv,
                                        Bb*Nn, 3*Cc, Cc);
    }
    // 2) layernorm + phi + split heads
    ln_phi_kernel<<<Bb*Nn, 512>>>(qw, qb, kw, kb);
    // 3) compressed keys
    kcmp_kernel<<<BHc*NBc, 64>>>();
    // 4) kv / z
    {
        dim3 grid(BHc, NCHUNK);
        kv_chunk_kernel<<<grid, 256>>>();
        int total = BHc*Dd*Dd + BHc*Dd;
        kv_reduce_kernel<<<(total + 255)/256, 256>>>();
    }
    // 5) router + topk
    router_topk_kernel<<<BHc*(Nn/8), 256>>>();
    // 6) sparse + linear attention
    attn_kernel<<<BHc*(Nn/8), 256>>>();
    // 7) out = attn @ w_proj + b_proj (2048 x 1024 x 1024)
    {
        dim3 grid(Cc/64, Bb*Nn/128);
        gemm_bias_kernel<<<grid, 256>>>((const float*)p_attn, w_proj, b_proj,
                                        out, Bb*Nn, Cc, Cc);
    }
    (void)in_sizes; (void)n_in; (void)out_size;
}

// round 2
// speedup vs baseline: 1.0782x; 1.0782x over previous
#include <cuda_runtime.h>
#include <math.h>
#include <stdint.h>

// Problem constants
#define Bb   2
#define Nn   1024
#define Cc   1024
#define Hh   16
#define Dd   64
#define BLKc 8
#define NBc  128
#define TOPKc 7
#define BHc  (Bb*Hh)          // 32
#define NCHUNK 16             // kv accumulation chunks
#define CHLEN (Nn/NCHUNK)     // 64

// ---------------- scratch (device globals; no allocation) ----------------
__device__ __align__(16) float g_qkv [Bb*Nn*3*Cc];        // (B,N,3C)
__device__ __align__(16) float g_q   [BHc*Nn*Dd];
__device__ __align__(16) float g_k   [BHc*Nn*Dd];
__device__ __align__(16) float g_v   [BHc*Nn*Dd];
__device__ __align__(16) float g_pq  [BHc*Nn*Dd];         // phi_q
__device__ __align__(16) float g_pk  [BHc*Nn*Dd];         // phi_k
__device__ __align__(16) float g_kcmp[BHc*NBc*Dd];
__device__               int   g_topk[BHc*Nn*TOPKc];
__device__ __align__(16) float g_kvp [NCHUNK*BHc*Dd*Dd];  // partial kv
__device__ __align__(16) float g_zp  [NCHUNK*BHc*Dd];     // partial z
__device__ __align__(16) float g_kv  [BHc*Dd*Dd];
__device__ __align__(16) float g_z   [BHc*Dd];
__device__ __align__(16) float g_attn[Bb*Nn*Cc];          // (B,N,C) pre-proj

// =============== tf32 tensor-core GEMM (3xTF32 for fp32 accuracy) ========
// C = A(MxK) @ B(KxN) + bias.  BM=128 BN=64 BK=16, 256 threads (8 warps),
// warp grid 4(M) x 2(N), warp tile 32x32 = 2 x 4 m16n8k8 fragments.
#define GBM 128
#define GBN 64
#define GBK 16
#define ASTR 136   // smem row stride (floats): 136 mod 32 == 8 -> conflict-free frags
#define BSTR 72    // 72 mod 32 == 8

__device__ __forceinline__ uint32_t f2tf32(float x) {
    uint32_t r;
    asm("cvt.rna.tf32.f32 %0, %1;" : "=r"(r) : "f"(x));
    return r;
}

__device__ __forceinline__ void mma_tf32(float* d, const uint32_t* a, const uint32_t* b) {
    asm volatile(
        "mma.sync.aligned.m16n8k8.row.col.f32.tf32.tf32.f32 "
        "{%0,%1,%2,%3}, {%4,%5,%6,%7}, {%8,%9}, {%0,%1,%2,%3};"
        : "+f"(d[0]), "+f"(d[1]), "+f"(d[2]), "+f"(d[3])
        : "r"(a[0]), "r"(a[1]), "r"(a[2]), "r"(a[3]), "r"(b[0]), "r"(b[1]));
}

__global__ __launch_bounds__(256) void gemm_tf32_kernel(
    const float* __restrict__ A, const float* __restrict__ B,
    const float* __restrict__ bias, float* __restrict__ C,
    int M, int N, int K)
{
    __shared__ float As[2][GBK*ASTR];
    __shared__ float Bs[2][GBK*BSTR];
    const int tid  = threadIdx.x;
    const int lane = tid & 31;
    const int warp = tid >> 5;
    const int warpM = warp & 3;
    const int warpN = warp >> 2;
    const int g  = lane >> 2;
    const int tq = lane & 3;
    const int bm = blockIdx.y * GBM;
    const int bn = blockIdx.x * GBN;

    // global load coords
    const int aR  = tid >> 1;           // A row within tile (0..127)
    const int aKq = (tid & 1) * 2;      // A k-quad base (0 or 2)
    const int bK  = tid >> 4;           // B k within tile (0..15)
    const int bN4 = (tid & 15) * 4;     // B col within tile

    float acc[2][4][4];
#pragma unroll
    for (int mf = 0; mf < 2; mf++)
#pragma unroll
        for (int nf = 0; nf < 4; nf++)
#pragma unroll
            for (int r = 0; r < 4; r++) acc[mf][nf][r] = 0.f;

    const int nIter = K / GBK;

    // ---- prologue: load tile 0 into smem buf 0 ----
    {
        float4 a0 = *reinterpret_cast<const float4*>(A + (size_t)(bm + aR) * K + (aKq + 0) * 4);
        float4 a1 = *reinterpret_cast<const float4*>(A + (size_t)(bm + aR) * K + (aKq + 1) * 4);
        float4 bv = *reinterpret_cast<const float4*>(B + (size_t)bK * N + bn + bN4);
        As[0][(aKq*4 + 0)*ASTR + aR] = a0.x;
        As[0][(aKq*4 + 1)*ASTR + aR] = a0.y;
        As[0][(aKq*4 + 2)*ASTR + aR] = a0.z;
        As[0][(aKq*4 + 3)*ASTR + aR] = a0.w;
        As[0][(aKq*4 + 4)*ASTR + aR] = a1.x;
        As[0][(aKq*4 + 5)*ASTR + aR] = a1.y;
        As[0][(aKq*4 + 6)*ASTR + aR] = a1.z;
        As[0][(aKq*4 + 7)*ASTR + aR] = a1.w;
        *reinterpret_cast<float4*>(&Bs[0][bK*BSTR + bN4]) = bv;
    }
    __syncthreads();

    for (int it = 0; it < nIter; it++) {
        const int buf = it & 1;
        float4 na0, na1, nb;
        const bool more = (it + 1 < nIter);
        if (more) {
            int k0 = (it + 1) * GBK;
            na0 = *reinterpret_cast<const float4*>(A + (size_t)(bm + aR) * K + k0 + (aKq + 0) * 4);
            na1 = *reinterpret_cast<const float4*>(A + (size_t)(bm + aR) * K + k0 + (aKq + 1) * 4);
            nb  = *reinterpret_cast<const float4*>(B + (size_t)(k0 + bK) * N + bn + bN4);
        }

        const float* as = As[buf];
        const float* bs = Bs[buf];
#pragma unroll
        for (int ks = 0; ks < 2; ks++) {
            const int kb = ks * 8;
            uint32_t ahi[2][4], alo[2][4];
#pragma unroll
            for (int mf = 0; mf < 2; mf++) {
                const int m = warpM * 32 + mf * 16 + g;
                const float* p = as + (kb + tq) * ASTR + m;
                float v0 = p[0];
                float v1 = p[8];
                float v2 = p[4*ASTR];
                float v3 = p[4*ASTR + 8];
                ahi[mf][0] = f2tf32(v0); alo[mf][0] = f2tf32(v0 - __uint_as_float(ahi[mf][0]));
                ahi[mf][1] = f2tf32(v1); alo[mf][1] = f2tf32(v1 - __uint_as_float(ahi[mf][1]));
                ahi[mf][2] = f2tf32(v2); alo[mf][2] = f2tf32(v2 - __uint_as_float(ahi[mf][2]));
                ahi[mf][3] = f2tf32(v3); alo[mf][3] = f2tf32(v3 - __uint_as_float(ahi[mf][3]));
            }
            uint32_t bhi[4][2], blo[4][2];
#pragma unroll
            for (int nf = 0; nf < 4; nf++) {
                const int n = warpN * 32 + nf * 8 + g;
                const float* p = bs + (kb + tq) * BSTR + n;
                float v0 = p[0];
                float v1 = p[4*BSTR];
                bhi[nf][0] = f2tf32(v0); blo[nf][0] = f2tf32(v0 - __uint_as_float(bhi[nf][0]));
                bhi[nf][1] = f2tf32(v1); blo[nf][1] = f2tf32(v1 - __uint_as_float(bhi[nf][1]));
            }
#pragma unroll
            for (int mf = 0; mf < 2; mf++)
#pragma unroll
                for (int nf = 0; nf < 4; nf++) mma_tf32(acc[mf][nf], ahi[mf], bhi[nf]);
#pragma unroll
            for (int mf = 0; mf < 2; mf++)
#pragma unroll
                for (int nf = 0; nf < 4; nf++) mma_tf32(acc[mf][nf], alo[mf], bhi[nf]);
#pragma unroll
            for (int mf = 0; mf < 2; mf++)
#pragma unroll
                for (int nf = 0; nf < 4; nf++) mma_tf32(acc[mf][nf], ahi[mf], blo[nf]);
        }

        if (more) {
            const int nbuf = buf ^ 1;
            As[nbuf][(aKq*4 + 0)*ASTR + aR] = na0.x;
            As[nbuf][(aKq*4 + 1)*ASTR + aR] = na0.y;
            As[nbuf][(aKq*4 + 2)*ASTR + aR] = na0.z;
            As[nbuf][(aKq*4 + 3)*ASTR + aR] = na0.w;
            As[nbuf][(aKq*4 + 4)*ASTR + aR] = na1.x;
            As[nbuf][(aKq*4 + 5)*ASTR + aR] = na1.y;
            As[nbuf][(aKq*4 + 6)*ASTR + aR] = na1.z;
            As[nbuf][(aKq*4 + 7)*ASTR + aR] = na1.w;
            *reinterpret_cast<float4*>(&Bs[nbuf][bK*BSTR + bN4]) = nb;
        }
        __syncthreads();
    }

    // ---- epilogue ----
#pragma unroll
    for (int mf = 0; mf < 2; mf++) {
#pragma unroll
        for (int nf = 0; nf < 4; nf++) {
            const int r0 = bm + warpM * 32 + mf * 16 + g;
            const int c0 = bn + warpN * 32 + nf * 8 + tq * 2;
            float2 bv = *reinterpret_cast<const float2*>(bias + c0);
            float2 o0 = make_float2(acc[mf][nf][0] + bv.x, acc[mf][nf][1] + bv.y);
            float2 o1 = make_float2(acc[mf][nf][2] + bv.x, acc[mf][nf][3] + bv.y);
            *reinterpret_cast<float2*>(C + (size_t)r0 * N + c0)       = o0;
            *reinterpret_cast<float2*>(C + (size_t)(r0 + 8) * N + c0) = o1;
        }
    }
}

// ------------- LayerNorm(q,k) + phi softmax + v copy, per (b,n) ----------
__global__ __launch_bounds__(512) void ln_phi_kernel(
    const float* __restrict__ qw, const float* __restrict__ qb,
    const float* __restrict__ kw, const float* __restrict__ kb)
{
    int bn = blockIdx.x;
    int b = bn / Nn, n = bn % Nn;
    int h = threadIdx.x >> 5;
    int lane = threadIdx.x & 31;
    const float* row = g_qkv + (size_t)bn * (3*Cc);
    int d0 = lane, d1 = lane + 32;
    size_t obase = ((size_t)(b*Hh + h) * Nn + n) * Dd;

    // ---- q ----
    {
        float v0 = row[h*Dd + d0], v1 = row[h*Dd + d1];
        float s = v0 + v1;
#pragma unroll
        for (int o = 16; o; o >>= 1) s += __shfl_xor_sync(~0u, s, o);
        float m = s * (1.f/64.f);
        float a0 = v0 - m, a1 = v1 - m;
        float vs = a0*a0 + a1*a1;
#pragma unroll
        for (int o = 16; o; o >>= 1) vs += __shfl_xor_sync(~0u, vs, o);
        float r = rsqrtf(vs * (1.f/64.f) + 1e-6f);
        float y0 = a0*r*qw[d0] + qb[d0];
        float y1 = a1*r*qw[d1] + qb[d1];
        g_q[obase + d0] = y0; g_q[obase + d1] = y1;
        float mx = fmaxf(y0, y1);
#pragma unroll
        for (int o = 16; o; o >>= 1) mx = fmaxf(mx, __shfl_xor_sync(~0u, mx, o));
        float e0 = __expf(y0 - mx), e1 = __expf(y1 - mx);
        float se = e0 + e1;
#pragma unroll
        for (int o = 16; o; o >>= 1) se += __shfl_xor_sync(~0u, se, o);
        float inv = 1.f / se;
        g_pq[obase + d0] = e0*inv; g_pq[obase + d1] = e1*inv;
    }
    // ---- k ----
    {
        float v0 = row[Cc + h*Dd + d0], v1 = row[Cc + h*Dd + d1];
        float s = v0 + v1;
#pragma unroll
        for (int o = 16; o; o >>= 1) s += __shfl_xor_sync(~0u, s, o);
        float m = s * (1.f/64.f);
        float a0 = v0 - m, a1 = v1 - m;
        float vs = a0*a0 + a1*a1;
#pragma unroll
        for (int o = 16; o; o >>= 1) vs += __shfl_xor_sync(~0u, vs, o);
        float r = rsqrtf(vs * (1.f/64.f) + 1e-6f);
        float y0 = a0*r*kw[d0] + kb[d0];
        float y1 = a1*r*kw[d1] + kb[d1];
        g_k[obase + d0] = y0; g_k[obase + d1] = y1;
        float mx = fmaxf(y0, y1);
#pragma unroll
        for (int o = 16; o; o >>= 1) mx = fmaxf(mx, __shfl_xor_sync(~0u, mx, o));
        float e0 = __expf(y0 - mx), e1 = __expf(y1 - mx);
        float se = e0 + e1;
#pragma unroll
        for (int o = 16; o; o >>= 1) se += __shfl_xor_sync(~0u, se, o);
        float inv = 1.f / se;
        g_pk[obase + d0] = e0*inv; g_pk[obase + d1] = e1*inv;
    }
    // ---- v copy ----
    g_v[obase + d0] = row[2*Cc + h*Dd + d0];
    g_v[obase + d1] = row[2*Cc + h*Dd + d1];
}

// ------------- compressed keys: mean pool over BLK=8 ---------------------
__global__ __launch_bounds__(64) void kcmp_kernel()
{
    int bhm = blockIdx.x;            // B*H*NB
    int d = threadIdx.x;
    int bh = bhm / NBc, m = bhm % NBc;
    const float* kr = g_k + ((size_t)bh*Nn + m*BLKc) * Dd;
    float s = 0.f;
#pragma unroll
    for (int t = 0; t < BLKc; t++) s += kr[t*Dd + d];
    g_kcmp[(size_t)bhm*Dd + d] = s * (1.f/BLKc);
}

// ------------- kv/z partials (deterministic, no atomics) -----------------
// grid (BH, NCHUNK), 256 threads; 4 tokens staged per sync round.
__global__ __launch_bounds__(256) void kv_chunk_kernel()
{
    int bh = blockIdx.x;
    int ch = blockIdx.y;
    int tid = threadIdx.x;
    int e = tid & 63;
    int dg = tid >> 6;               // 0..3
    __shared__ float sh[4][128];
    float acc[16];
#pragma unroll
    for (int j = 0; j < 16; j++) acc[j] = 0.f;
    float zacc = 0.f;
    size_t base = (size_t)bh * Nn * Dd;
    const int lr = tid >> 6;         // staged row 0..3
    const int lc = (tid & 63) * 2;   // 0..126 step 2
    for (int i0 = 0; i0 < CHLEN; i0 += 4) {
        __syncthreads();
        {
            int n = ch * CHLEN + i0 + lr;
            float2 val;
            if (lc < 64)
                val = *reinterpret_cast<const float2*>(g_pk + base + (size_t)n*Dd + lc);
            else
                val = *reinterpret_cast<const float2*>(g_v + base + (size_t)n*Dd + (lc - 64));
            sh[lr][lc]   = val.x;
            sh[lr][lc+1] = val.y;
        }
        __syncthreads();
#pragma unroll
        for (int r = 0; r < 4; r++) {
            float ve = sh[r][64 + e];
#pragma unroll
            for (int j = 0; j < 16; j++) acc[j] += sh[r][dg*16 + j] * ve;
            if (tid < 64) zacc += sh[r][tid];
        }
    }
    float* out = g_kvp + ((size_t)ch * BHc + bh) * (Dd*Dd);
#pragma unroll
    for (int j = 0; j < 16; j++) out[(dg*16 + j)*Dd + e] = acc[j];
    if (tid < 64) g_zp[((size_t)ch * BHc + bh) * Dd + tid] = zacc;
}

__global__ __launch_bounds__(256) void kv_reduce_kernel()
{
    int idx = blockIdx.x * 256 + threadIdx.x;
    const int KVN = BHc*Dd*Dd;       // 131072
    const int ZN  = BHc*Dd;          // 2048
    if (idx < KVN) {
        float s = 0.f;
#pragma unroll
        for (int c = 0; c < NCHUNK; c++) s += g_kvp[(size_t)c*KVN + idx];
        g_kv[idx] = s;
    } else if (idx < KVN + ZN) {
        int z = idx - KVN;
        float s = 0.f;
#pragma unroll
        for (int c = 0; c < NCHUNK; c++) s += g_zp[(size_t)c*ZN + z];
        g_z[z] = s;
    }
}

// ------------- router + top-7 : warp per query ---------------------------
__global__ __launch_bounds__(256) void router_topk_kernel()
{
    int bh = blockIdx.x / (Nn/8);
    int n0 = (blockIdx.x % (Nn/8)) * 8;
    int warp = threadIdx.x >> 5;
    int lane = threadIdx.x & 31;
    int n = n0 + warp;
    __shared__ float sq[8][64];
    const float* qrow = g_q + ((size_t)bh*Nn + n) * Dd;
    sq[warp][lane]      = qrow[lane];
    sq[warp][lane + 32] = qrow[lane + 32];
    __syncwarp();
    const float scale = 0.125f;      // D^-0.5
    const float* kc = g_kcmp + (size_t)bh * NBc * Dd;
    float s0, s1, s2, s3;
    {
        float a0=0.f, a1=0.f, a2=0.f, a3=0.f;
        const float* r0 = kc + (lane*4 + 0) * Dd;
        const float* r1 = kc + (lane*4 + 1) * Dd;
        const float* r2 = kc + (lane*4 + 2) * Dd;
        const float* r3 = kc + (lane*4 + 3) * Dd;
#pragma unroll
        for (int d = 0; d < 64; d++) {
            float qd = sq[warp][d];
            a0 += qd * __ldg(r0 + d);
            a1 += qd * __ldg(r1 + d);
            a2 += qd * __ldg(r2 + d);
            a3 += qd * __ldg(r3 + d);
        }
        s0 = a0*scale; s1 = a1*scale; s2 = a2*scale; s3 = a3*scale;
    }
    int qidx = bh * Nn + n;
    const float NEGINF = -__int_as_float(0x7f800000);
#pragma unroll
    for (int r = 0; r < TOPKc; r++) {
        float bv = s0; int bj = 0;
        if (s1 > bv) { bv = s1; bj = 1; }
        if (s2 > bv) { bv = s2; bj = 2; }
        if (s3 > bv) { bv = s3; bj = 3; }
        int bm = lane*4 + bj;
#pragma unroll
        for (int o = 16; o; o >>= 1) {
            float ov = __shfl_xor_sync(~0u, bv, o);
            int   om = __shfl_xor_sync(~0u, bm, o);
            if (ov > bv || (ov == bv && om < bm)) { bv = ov; bm = om; }
        }
        if ((bm >> 2) == lane) {
            int j = bm & 3;
            if      (j == 0) s0 = NEGINF;
            else if (j == 1) s1 = NEGINF;
            else if (j == 2) s2 = NEGINF;
            else             s3 = NEGINF;
        }
        if (lane == 0) g_topk[(size_t)qidx*TOPKc + r] = bm;
    }
}

// ------------- fused sparse softmax attention + linear branch ------------
__global__ __launch_bounds__(256) void attn_kernel()
{
    int bh = blockIdx.x / (Nn/8);
    int b = bh / Hh, h = bh % Hh;
    int n0 = (blockIdx.x % (Nn/8)) * 8;
    int warp = threadIdx.x >> 5;
    int lane = threadIdx.x & 31;
    int n = n0 + warp;
    __shared__ float sq [8][64];
    __shared__ float spq[8][64];
    __shared__ float sp [8][64];
    __shared__ int   sblk[8][8];

    size_t qb = ((size_t)bh*Nn + n) * Dd;
    sq [warp][lane]      = g_q [qb + lane];
    sq [warp][lane + 32] = g_q [qb + lane + 32];
    spq[warp][lane]      = g_pq[qb + lane];
    spq[warp][lane + 32] = g_pq[qb + lane + 32];
    if (lane < TOPKc) sblk[warp][lane] = g_topk[((size_t)bh*Nn + n)*TOPKc + lane];
    __syncwarp();

    const float scale = 0.125f;
    const int NSEL = TOPKc * BLKc;   // 56
    const float NEGINF = -__int_as_float(0x7f800000);

    float l0, l1;
    {
        int s = lane;
        int tok = sblk[warp][s >> 3] * BLKc + (s & 7);
        const float* kr = g_k + ((size_t)bh*Nn + tok) * Dd;
        float a = 0.f;
#pragma unroll
        for (int d = 0; d < 64; d++) a += sq[warp][d] * __ldg(kr + d);
        l0 = a * scale;
    }
    {
        int s = lane + 32;
        if (s < NSEL) {
            int tok = sblk[warp][s >> 3] * BLKc + (s & 7);
            const float* kr = g_k + ((size_t)bh*Nn + tok) * Dd;
            float a = 0.f;
#pragma unroll
            for (int d = 0; d < 64; d++) a += sq[warp][d] * __ldg(kr + d);
            l1 = a * scale;
        } else l1 = NEGINF;
    }
    float mx = fmaxf(l0, l1);
#pragma unroll
    for (int o = 16; o; o >>= 1) mx = fmaxf(mx, __shfl_xor_sync(~0u, mx, o));
    float e0 = __expf(l0 - mx);
    float e1 = (lane + 32 < NSEL) ? __expf(l1 - mx) : 0.f;
    float se = e0 + e1;
#pragma unroll
    for (int o = 16; o; o >>= 1) se += __shfl_xor_sync(~0u, se, o);
    float inv = 1.f / se;
    sp[warp][lane]      = e0 * inv;
    sp[warp][lane + 32] = e1 * inv;
    __syncwarp();

    int d0 = lane, d1 = lane + 32;
    float a0 = 0.f, a1 = 0.f;
#pragma unroll
    for (int s = 0; s < NSEL; s++) {
        int tok = sblk[warp][s >> 3] * BLKc + (s & 7);
        const float* vr = g_v + ((size_t)bh*Nn + tok) * Dd;
        float p = sp[warp][s];
        a0 += p * vr[d0];
        a1 += p * vr[d1];
    }

    const float* zr = g_z + (size_t)bh * Dd;
    float t = spq[warp][d0]*zr[d0] + spq[warp][d1]*zr[d1];
#pragma unroll
    for (int o = 16; o; o >>= 1) t += __shfl_xor_sync(~0u, t, o);
    float inv_den = 1.f / (t + 1e-6f);
    const float* kvm = g_kv + (size_t)bh * Dd * Dd;
    float n0a = 0.f, n1a = 0.f;
#pragma unroll
    for (int e = 0; e < 64; e++) {
        float pe = spq[warp][e];
        n0a += pe * kvm[e*Dd + d0];
        n1a += pe * kvm[e*Dd + d1];
    }
    size_t ob = ((size_t)(b*Nn + n)) * Cc + h*Dd;
    g_attn[ob + d0] = a0 + n0a * inv_den;
    g_attn[ob + d1] = a1 + n1a * inv_den;
}

// ---------------------------------------------------------------------------
extern "C" void kernel_launch(void* const* d_in, const int* in_sizes, int n_in,
                              void* d_out, int out_size)
{
    const float* x      = (const float*)d_in[0];
    const float* w_qkv  = (const float*)d_in[1];
    const float* b_qkv  = (const float*)d_in[2];
    const float* qw     = (const float*)d_in[3];
    const float* qb     = (const float*)d_in[4];
    const float* kw     = (const float*)d_in[5];
    const float* kb     = (const float*)d_in[6];
    const float* w_proj = (const float*)d_in[7];
    const float* b_proj = (const float*)d_in[8];
    float* out = (float*)d_out;

    void *p_qkv = nullptr, *p_attn = nullptr;
    cudaGetSymbolAddress(&p_qkv,  g_qkv);
    cudaGetSymbolAddress(&p_attn, g_attn);

    // 1) qkv = x @ w_qkv + b_qkv      (2048 x 3072 x 1024)
    {
        dim3 grid(3*Cc/GBN, Bb*Nn/GBM);
        gemm_tf32_kernel<<<grid, 256>>>(x, w_qkv, b_qkv, (float*)p_qkv,
                                        Bb*Nn, 3*Cc, Cc);
    }
    // 2) layernorm + phi + split heads
    ln_phi_kernel<<<Bb*Nn, 512>>>(qw, qb, kw, kb);
    // 3) compressed keys
    kcmp_kernel<<<BHc*NBc, 64>>>();
    // 4) kv / z
    {
        dim3 grid(BHc, NCHUNK);
        kv_chunk_kernel<<<grid, 256>>>();
        int total = BHc*Dd*Dd + BHc*Dd;
        kv_reduce_kernel<<<(total + 255)/256, 256>>>();
    }
    // 5) router + topk
    router_topk_kernel<<<BHc*(Nn/8), 256>>>();
    // 6) sparse + linear attention
    attn_kernel<<<BHc*(Nn/8), 256>>>();
    // 7) out = attn @ w_proj + b_proj (2048 x 1024 x 1024)
    {
        dim3 grid(Cc/GBN, Bb*Nn/GBM);
        gemm_tf32_kernel<<<grid, 256>>>((const float*)p_attn, w_proj, b_proj,
                                        out, Bb*Nn, Cc, Cc);
    }
    (void)in_sizes; (void)n_in; (void)out_size;
}

// round 3
// speedup vs baseline: 2.9961x; 2.7787x over previous
#include <cuda_runtime.h>
#include <math.h>
#include <stdint.h>

// Problem constants
#define Bb   2
#define Nn   1024
#define Cc   1024
#define Hh   16
#define Dd   64
#define BLKc 8
#define NBc  128
#define TOPKc 7
#define BHc  (Bb*Hh)          // 32
#define NCHUNK 16             // kv accumulation chunks
#define CHLEN (Nn/NCHUNK)     // 64

// ---------------- scratch (device globals; no allocation) ----------------
__device__ __align__(16) float g_qkv [Bb*Nn*3*Cc];        // (B,N,3C)
__device__ __align__(16) float g_q   [BHc*Nn*Dd];
__device__ __align__(16) float g_k   [BHc*Nn*Dd];
__device__ __align__(16) float g_v   [BHc*Nn*Dd];
__device__ __align__(16) float g_pq  [BHc*Nn*Dd];         // phi_q
__device__ __align__(16) float g_pk  [BHc*Nn*Dd];         // phi_k
__device__ __align__(16) float g_kcmp[BHc*NBc*Dd];
__device__               int   g_topk[BHc*Nn*TOPKc];
__device__ __align__(16) float g_kvp [NCHUNK*BHc*Dd*Dd];  // partial kv
__device__ __align__(16) float g_zp  [NCHUNK*BHc*Dd];     // partial z
__device__ __align__(16) float g_kv  [BHc*Dd*Dd];
__device__ __align__(16) float g_z   [BHc*Dd];
__device__ __align__(16) float g_attn[Bb*Nn*Cc];          // (B,N,C) pre-proj

// =============== tf32 tensor-core GEMM (3xTF32 for fp32 accuracy) ========
#define GBM 128
#define GBN 64
#define GBK 16
#define ASTR 136
#define BSTR 72

__device__ __forceinline__ uint32_t f2tf32(float x) {
    uint32_t r;
    asm("cvt.rna.tf32.f32 %0, %1;" : "=r"(r) : "f"(x));
    return r;
}

__device__ __forceinline__ void mma_tf32(float* d, const uint32_t* a, const uint32_t* b) {
    asm volatile(
        "mma.sync.aligned.m16n8k8.row.col.f32.tf32.tf32.f32 "
        "{%0,%1,%2,%3}, {%4,%5,%6,%7}, {%8,%9}, {%0,%1,%2,%3};"
        : "+f"(d[0]), "+f"(d[1]), "+f"(d[2]), "+f"(d[3])
        : "r"(a[0]), "r"(a[1]), "r"(a[2]), "r"(a[3]), "r"(b[0]), "r"(b[1]));
}

__global__ __launch_bounds__(256) void gemm_tf32_kernel(
    const float* __restrict__ A, const float* __restrict__ B,
    const float* __restrict__ bias, float* __restrict__ C,
    int M, int N, int K)
{
    __shared__ float As[2][GBK*ASTR];
    __shared__ float Bs[2][GBK*BSTR];
    const int tid  = threadIdx.x;
    const int lane = tid & 31;
    const int warp = tid >> 5;
    const int warpM = warp & 3;
    const int warpN = warp >> 2;
    const int g  = lane >> 2;
    const int tq = lane & 3;
    const int bm = blockIdx.y * GBM;
    const int bn = blockIdx.x * GBN;

    const int aR  = tid >> 1;
    const int aKq = (tid & 1) * 2;
    const int bK  = tid >> 4;
    const int bN4 = (tid & 15) * 4;

    float acc[2][4][4];
#pragma unroll
    for (int mf = 0; mf < 2; mf++)
#pragma unroll
        for (int nf = 0; nf < 4; nf++)
#pragma unroll
            for (int r = 0; r < 4; r++) acc[mf][nf][r] = 0.f;

    const int nIter = K / GBK;

    {
        float4 a0 = *reinterpret_cast<const float4*>(A + (size_t)(bm + aR) * K + (aKq + 0) * 4);
        float4 a1 = *reinterpret_cast<const float4*>(A + (size_t)(bm + aR) * K + (aKq + 1) * 4);
        float4 bv = *reinterpret_cast<const float4*>(B + (size_t)bK * N + bn + bN4);
        As[0][(aKq*4 + 0)*ASTR + aR] = a0.x;
        As[0][(aKq*4 + 1)*ASTR + aR] = a0.y;
        As[0][(aKq*4 + 2)*ASTR + aR] = a0.z;
        As[0][(aKq*4 + 3)*ASTR + aR] = a0.w;
        As[0][(aKq*4 + 4)*ASTR + aR] = a1.x;
        As[0][(aKq*4 + 5)*ASTR + aR] = a1.y;
        As[0][(aKq*4 + 6)*ASTR + aR] = a1.z;
        As[0][(aKq*4 + 7)*ASTR + aR] = a1.w;
        *reinterpret_cast<float4*>(&Bs[0][bK*BSTR + bN4]) = bv;
    }
    __syncthreads();

    for (int it = 0; it < nIter; it++) {
        const int buf = it & 1;
        float4 na0, na1, nb;
        const bool more = (it + 1 < nIter);
        if (more) {
            int k0 = (it + 1) * GBK;
            na0 = *reinterpret_cast<const float4*>(A + (size_t)(bm + aR) * K + k0 + (aKq + 0) * 4);
            na1 = *reinterpret_cast<const float4*>(A + (size_t)(bm + aR) * K + k0 + (aKq + 1) * 4);
            nb  = *reinterpret_cast<const float4*>(B + (size_t)(k0 + bK) * N + bn + bN4);
        }

        const float* as = As[buf];
        const float* bs = Bs[buf];
#pragma unroll
        for (int ks = 0; ks < 2; ks++) {
            const int kb = ks * 8;
            uint32_t ahi[2][4], alo[2][4];
#pragma unroll
            for (int mf = 0; mf < 2; mf++) {
                const int m = warpM * 32 + mf * 16 + g;
                const float* p = as + (kb + tq) * ASTR + m;
                float v0 = p[0];
                float v1 = p[8];
                float v2 = p[4*ASTR];
                float v3 = p[4*ASTR + 8];
                ahi[mf][0] = f2tf32(v0); alo[mf][0] = f2tf32(v0 - __uint_as_float(ahi[mf][0]));
                ahi[mf][1] = f2tf32(v1); alo[mf][1] = f2tf32(v1 - __uint_as_float(ahi[mf][1]));
                ahi[mf][2] = f2tf32(v2); alo[mf][2] = f2tf32(v2 - __uint_as_float(ahi[mf][2]));
                ahi[mf][3] = f2tf32(v3); alo[mf][3] = f2tf32(v3 - __uint_as_float(ahi[mf][3]));
            }
            uint32_t bhi[4][2], blo[4][2];
#pragma unroll
            for (int nf = 0; nf < 4; nf++) {
                const int n = warpN * 32 + nf * 8 + g;
                const float* p = bs + (kb + tq) * BSTR + n;
                float v0 = p[0];
                float v1 = p[4*BSTR];
                bhi[nf][0] = f2tf32(v0); blo[nf][0] = f2tf32(v0 - __uint_as_float(bhi[nf][0]));
                bhi[nf][1] = f2tf32(v1); blo[nf][1] = f2tf32(v1 - __uint_as_float(bhi[nf][1]));
            }
#pragma unroll
            for (int mf = 0; mf < 2; mf++)
#pragma unroll
                for (int nf = 0; nf < 4; nf++) mma_tf32(acc[mf][nf], ahi[mf], bhi[nf]);
#pragma unroll
            for (int mf = 0; mf < 2; mf++)
#pragma unroll
                for (int nf = 0; nf < 4; nf++) mma_tf32(acc[mf][nf], alo[mf], bhi[nf]);
#pragma unroll
            for (int mf = 0; mf < 2; mf++)
#pragma unroll
                for (int nf = 0; nf < 4; nf++) mma_tf32(acc[mf][nf], ahi[mf], blo[nf]);
        }

        if (more) {
            const int nbuf = buf ^ 1;
            As[nbuf][(aKq*4 + 0)*ASTR + aR] = na0.x;
            As[nbuf][(aKq*4 + 1)*ASTR + aR] = na0.y;
            As[nbuf][(aKq*4 + 2)*ASTR + aR] = na0.z;
            As[nbuf][(aKq*4 + 3)*ASTR + aR] = na0.w;
            As[nbuf][(aKq*4 + 4)*ASTR + aR] = na1.x;
            As[nbuf][(aKq*4 + 5)*ASTR + aR] = na1.y;
            As[nbuf][(aKq*4 + 6)*ASTR + aR] = na1.z;
            As[nbuf][(aKq*4 + 7)*ASTR + aR] = na1.w;
            *reinterpret_cast<float4*>(&Bs[nbuf][bK*BSTR + bN4]) = nb;
        }
        __syncthreads();
    }

#pragma unroll
    for (int mf = 0; mf < 2; mf++) {
#pragma unroll
        for (int nf = 0; nf < 4; nf++) {
            const int r0 = bm + warpM * 32 + mf * 16 + g;
            const int c0 = bn + warpN * 32 + nf * 8 + tq * 2;
            float2 bv = *reinterpret_cast<const float2*>(bias + c0);
            float2 o0 = make_float2(acc[mf][nf][0] + bv.x, acc[mf][nf][1] + bv.y);
            float2 o1 = make_float2(acc[mf][nf][2] + bv.x, acc[mf][nf][3] + bv.y);
            *reinterpret_cast<float2*>(C + (size_t)r0 * N + c0)       = o0;
            *reinterpret_cast<float2*>(C + (size_t)(r0 + 8) * N + c0) = o1;
        }
    }
}

// ------------- LayerNorm(q,k) + phi softmax + v copy, per (b,n) ----------
__global__ __launch_bounds__(512) void ln_phi_kernel(
    const float* __restrict__ qw, const float* __restrict__ qb,
    const float* __restrict__ kw, const float* __restrict__ kb)
{
    int bn = blockIdx.x;
    int b = bn / Nn, n = bn % Nn;
    int h = threadIdx.x >> 5;
    int lane = threadIdx.x & 31;
    const float* row = g_qkv + (size_t)bn * (3*Cc);
    int d0 = lane, d1 = lane + 32;
    size_t obase = ((size_t)(b*Hh + h) * Nn + n) * Dd;

    // ---- q ----
    {
        float v0 = row[h*Dd + d0], v1 = row[h*Dd + d1];
        float s = v0 + v1;
#pragma unroll
        for (int o = 16; o; o >>= 1) s += __shfl_xor_sync(~0u, s, o);
        float m = s * (1.f/64.f);
        float a0 = v0 - m, a1 = v1 - m;
        float vs = a0*a0 + a1*a1;
#pragma unroll
        for (int o = 16; o; o >>= 1) vs += __shfl_xor_sync(~0u, vs, o);
        float r = rsqrtf(vs * (1.f/64.f) + 1e-6f);
        float y0 = a0*r*qw[d0] + qb[d0];
        float y1 = a1*r*qw[d1] + qb[d1];
        g_q[obase + d0] = y0; g_q[obase + d1] = y1;
        float mx = fmaxf(y0, y1);
#pragma unroll
        for (int o = 16; o; o >>= 1) mx = fmaxf(mx, __shfl_xor_sync(~0u, mx, o));
        float e0 = __expf(y0 - mx), e1 = __expf(y1 - mx);
        float se = e0 + e1;
#pragma unroll
        for (int o = 16; o; o >>= 1) se += __shfl_xor_sync(~0u, se, o);
        float inv = 1.f / se;
        g_pq[obase + d0] = e0*inv; g_pq[obase + d1] = e1*inv;
    }
    // ---- k ----
    {
        float v0 = row[Cc + h*Dd + d0], v1 = row[Cc + h*Dd + d1];
        float s = v0 + v1;
#pragma unroll
        for (int o = 16; o; o >>= 1) s += __shfl_xor_sync(~0u, s, o);
        float m = s * (1.f/64.f);
        float a0 = v0 - m, a1 = v1 - m;
        float vs = a0*a0 + a1*a1;
#pragma unroll
        for (int o = 16; o; o >>= 1) vs += __shfl_xor_sync(~0u, vs, o);
        float r = rsqrtf(vs * (1.f/64.f) + 1e-6f);
        float y0 = a0*r*kw[d0] + kb[d0];
        float y1 = a1*r*kw[d1] + kb[d1];
        g_k[obase + d0] = y0; g_k[obase + d1] = y1;
        float mx = fmaxf(y0, y1);
#pragma unroll
        for (int o = 16; o; o >>= 1) mx = fmaxf(mx, __shfl_xor_sync(~0u, mx, o));
        float e0 = __expf(y0 - mx), e1 = __expf(y1 - mx);
        float se = e0 + e1;
#pragma unroll
        for (int o = 16; o; o >>= 1) se += __shfl_xor_sync(~0u, se, o);
        float inv = 1.f / se;
        g_pk[obase + d0] = e0*inv; g_pk[obase + d1] = e1*inv;
    }
    // ---- v copy ----
    g_v[obase + d0] = row[2*Cc + h*Dd + d0];
    g_v[obase + d1] = row[2*Cc + h*Dd + d1];
}

// ------------- compressed keys: mean pool over BLK=8 ---------------------
__global__ __launch_bounds__(64) void kcmp_kernel()
{
    int bhm = blockIdx.x;            // B*H*NB
    int d = threadIdx.x;
    int bh = bhm / NBc, m = bhm % NBc;
    const float* kr = g_k + ((size_t)bh*Nn + m*BLKc) * Dd;
    float s = 0.f;
#pragma unroll
    for (int t = 0; t < BLKc; t++) s += kr[t*Dd + d];
    g_kcmp[(size_t)bhm*Dd + d] = s * (1.f/BLKc);
}

// ------------- kv/z partials (deterministic, no atomics) -----------------
__global__ __launch_bounds__(256) void kv_chunk_kernel()
{
    int bh = blockIdx.x;
    int ch = blockIdx.y;
    int tid = threadIdx.x;
    int e = tid & 63;
    int dg = tid >> 6;               // 0..3
    __shared__ float sh[4][128];
    float acc[16];
#pragma unroll
    for (int j = 0; j < 16; j++) acc[j] = 0.f;
    float zacc = 0.f;
    size_t base = (size_t)bh * Nn * Dd;
    const int lr = tid >> 6;
    const int lc = (tid & 63) * 2;
    for (int i0 = 0; i0 < CHLEN; i0 += 4) {
        __syncthreads();
        {
            int n = ch * CHLEN + i0 + lr;
            float2 val;
            if (lc < 64)
                val = *reinterpret_cast<const float2*>(g_pk + base + (size_t)n*Dd + lc);
            else
                val = *reinterpret_cast<const float2*>(g_v + base + (size_t)n*Dd + (lc - 64));
            sh[lr][lc]   = val.x;
            sh[lr][lc+1] = val.y;
        }
        __syncthreads();
#pragma unroll
        for (int r = 0; r < 4; r++) {
            float ve = sh[r][64 + e];
#pragma unroll
            for (int j = 0; j < 16; j++) acc[j] += sh[r][dg*16 + j] * ve;
            if (tid < 64) zacc += sh[r][tid];
        }
    }
    float* out = g_kvp + ((size_t)ch * BHc + bh) * (Dd*Dd);
#pragma unroll
    for (int j = 0; j < 16; j++) out[(dg*16 + j)*Dd + e] = acc[j];
    if (tid < 64) g_zp[((size_t)ch * BHc + bh) * Dd + tid] = zacc;
}

__global__ __launch_bounds__(256) void kv_reduce_kernel()
{
    int idx = blockIdx.x * 256 + threadIdx.x;
    const int KVN = BHc*Dd*Dd;
    const int ZN  = BHc*Dd;
    if (idx < KVN) {
        float s = 0.f;
#pragma unroll
        for (int c = 0; c < NCHUNK; c++) s += g_kvp[(size_t)c*KVN + idx];
        g_kv[idx] = s;
    } else if (idx < KVN + ZN) {
        int z = idx - KVN;
        float s = 0.f;
#pragma unroll
        for (int c = 0; c < NCHUNK; c++) s += g_zp[(size_t)c*ZN + z];
        g_z[z] = s;
    }
}

// ------------- router + top-7 v2 : smem-transposed kcmp ------------------
// grid = BH * (N/64), 256 threads = 8 warps; each warp does 8 queries.
#define KCSTR 132   // row stride (floats), 16B multiple, conflict-free LDS.128
__global__ __launch_bounds__(256) void router_topk_kernel()
{
    __shared__ float kct[Dd * KCSTR];   // [d][blk], 33.8KB
    int bh = blockIdx.x >> 4;           // Nn/64 = 16 query tiles
    int n0 = (blockIdx.x & 15) * 64;
    int tid = threadIdx.x;
    int warp = tid >> 5, lane = tid & 31;

    // transpose-load kcmp (coalesced global reads)
    const float* kc = g_kcmp + (size_t)bh * NBc * Dd;
#pragma unroll
    for (int i = 0; i < 32; i++) {
        int idx = tid + i * 256;        // 0..8191
        int blk = idx >> 6, d = idx & 63;
        kct[d * KCSTR + blk] = kc[idx];
    }
    __syncthreads();

    const float scale = 0.125f;
    const float NEGINF = -__int_as_float(0x7f800000);

    for (int qi = 0; qi < 8; qi++) {
        int n = n0 + warp * 8 + qi;
        const float* qrow = g_q + ((size_t)bh*Nn + n) * Dd;
        float q0 = qrow[lane], q1 = qrow[lane + 32];
        float s0 = 0.f, s1 = 0.f, s2 = 0.f, s3 = 0.f;
#pragma unroll
        for (int d = 0; d < 64; d++) {
            float qd = (d < 32) ? __shfl_sync(~0u, q0, d)
                                : __shfl_sync(~0u, q1, d - 32);
            float4 kv4 = *reinterpret_cast<const float4*>(&kct[d * KCSTR + lane * 4]);
            s0 += qd * kv4.x; s1 += qd * kv4.y;
            s2 += qd * kv4.z; s3 += qd * kv4.w;
        }
        s0 *= scale; s1 *= scale; s2 *= scale; s3 *= scale;

        int qidx = bh * Nn + n;
#pragma unroll
        for (int r = 0; r < TOPKc; r++) {
            float bv = s0; int bj = 0;
            if (s1 > bv) { bv = s1; bj = 1; }
            if (s2 > bv) { bv = s2; bj = 2; }
            if (s3 > bv) { bv = s3; bj = 3; }
            int bm = lane * 4 + bj;
#pragma unroll
            for (int o = 16; o; o >>= 1) {
                float ov = __shfl_xor_sync(~0u, bv, o);
                int   om = __shfl_xor_sync(~0u, bm, o);
                if (ov > bv || (ov == bv && om < bm)) { bv = ov; bm = om; }
            }
            if ((bm >> 2) == lane) {
                int j = bm & 3;
                if      (j == 0) s0 = NEGINF;
                else if (j == 1) s1 = NEGINF;
                else if (j == 2) s2 = NEGINF;
                else             s3 = NEGINF;
            }
            if (lane == 0) g_topk[(size_t)qidx*TOPKc + r] = bm;
        }
    }
}

// ------------- fused sparse softmax attention + linear branch ------------
__global__ __launch_bounds__(256) void attn_kernel()
{
    int bh = blockIdx.x / (Nn/8);
    int b = bh / Hh, h = bh % Hh;
    int n0 = (blockIdx.x % (Nn/8)) * 8;
    int warp = threadIdx.x >> 5;
    int lane = threadIdx.x & 31;
    int n = n0 + warp;
    __shared__ float sq [8][64];
    __shared__ float spq[8][64];
    __shared__ float sp [8][64];
    __shared__ int   sblk[8][8];

    size_t qb = ((size_t)bh*Nn + n) * Dd;
    {
        float2 a = *reinterpret_cast<const float2*>(g_q  + qb + lane*2);
        float2 c = *reinterpret_cast<const float2*>(g_pq + qb + lane*2);
        sq [warp][lane*2] = a.x; sq [warp][lane*2+1] = a.y;
        spq[warp][lane*2] = c.x; spq[warp][lane*2+1] = c.y;
    }
    if (lane < TOPKc) sblk[warp][lane] = g_topk[((size_t)bh*Nn + n)*TOPKc + lane];
    __syncwarp();

    const float scale = 0.125f;
    const int NSEL = TOPKc * BLKc;   // 56
    const float NEGINF = -__int_as_float(0x7f800000);
    const float4* sq4 = reinterpret_cast<const float4*>(sq[warp]);

    float l0, l1;
    {
        int s = lane;
        int tok = sblk[warp][s >> 3] * BLKc + (s & 7);
        const float4* kr4 = reinterpret_cast<const float4*>(
            g_k + ((size_t)bh*Nn + tok) * Dd);
        float a = 0.f;
#pragma unroll
        for (int t = 0; t < 16; t++) {
            float4 qv = sq4[t];
            float4 kv = __ldg(kr4 + t);
            a += qv.x*kv.x + qv.y*kv.y + qv.z*kv.z + qv.w*kv.w;
        }
        l0 = a * scale;
    }
    {
        int s = lane + 32;
        if (s < NSEL) {
            int tok = sblk[warp][s >> 3] * BLKc + (s & 7);
            const float4* kr4 = reinterpret_cast<const float4*>(
                g_k + ((size_t)bh*Nn + tok) * Dd);
            float a = 0.f;
#pragma unroll
            for (int t = 0; t < 16; t++) {
                float4 qv = sq4[t];
                float4 kv = __ldg(kr4 + t);
                a += qv.x*kv.x + qv.y*kv.y + qv.z*kv.z + qv.w*kv.w;
            }
            l1 = a * scale;
        } else l1 = NEGINF;
    }
    float mx = fmaxf(l0, l1);
#pragma unroll
    for (int o = 16; o; o >>= 1) mx = fmaxf(mx, __shfl_xor_sync(~0u, mx, o));
    float e0 = __expf(l0 - mx);
    float e1 = (lane + 32 < NSEL) ? __expf(l1 - mx) : 0.f;
    float se = e0 + e1;
#pragma unroll
    for (int o = 16; o; o >>= 1) se += __shfl_xor_sync(~0u, se, o);
    float inv = 1.f / se;
    sp[warp][lane]      = e0 * inv;
    sp[warp][lane + 32] = e1 * inv;
    __syncwarp();

    int d0 = lane, d1 = lane + 32;
    float a0 = 0.f, a1 = 0.f;
#pragma unroll
    for (int s = 0; s < NSEL; s++) {
        int tok = sblk[warp][s >> 3] * BLKc + (s & 7);
        const float* vr = g_v + ((size_t)bh*Nn + tok) * Dd;
        float p = sp[warp][s];
        a0 += p * vr[d0];
        a1 += p * vr[d1];
    }

    const float* zr = g_z + (size_t)bh * Dd;
    float t = spq[warp][d0]*zr[d0] + spq[warp][d1]*zr[d1];
#pragma unroll
    for (int o = 16; o; o >>= 1) t += __shfl_xor_sync(~0u, t, o);
    float inv_den = 1.f / (t + 1e-6f);
    const float* kvm = g_kv + (size_t)bh * Dd * Dd;
    float n0a = 0.f, n1a = 0.f;
#pragma unroll
    for (int e = 0; e < 64; e++) {
        float pe = spq[warp][e];
        n0a += pe * kvm[e*Dd + d0];
        n1a += pe * kvm[e*Dd + d1];
    }
    size_t ob = ((size_t)(b*Nn + n)) * Cc + h*Dd;
    g_attn[ob + d0] = a0 + n0a * inv_den;
    g_attn[ob + d1] = a1 + n1a * inv_den;
}

// ---------------------------------------------------------------------------
extern "C" void kernel_launch(void* const* d_in, const int* in_sizes, int n_in,
                              void* d_out, int out_size)
{
    const float* x      = (const float*)d_in[0];
    const float* w_qkv  = (const float*)d_in[1];
    const float* b_qkv  = (const float*)d_in[2];
    const float* qw     = (const float*)d_in[3];
    const float* qb     = (const float*)d_in[4];
    const float* kw     = (const float*)d_in[5];
    const float* kb     = (const float*)d_in[6];
    const float* w_proj = (const float*)d_in[7];
    const float* b_proj = (const float*)d_in[8];
    float* out = (float*)d_out;

    void *p_qkv = nullptr, *p_attn = nullptr;
    cudaGetSymbolAddress(&p_qkv,  g_qkv);
    cudaGetSymbolAddress(&p_attn, g_attn);

    // 1) qkv = x @ w_qkv + b_qkv
    {
        dim3 grid(3*Cc/GBN, Bb*Nn/GBM);
        gemm_tf32_kernel<<<grid, 256>>>(x, w_qkv, b_qkv, (float*)p_qkv,
                                        Bb*Nn, 3*Cc, Cc);
    }
    // 2) layernorm + phi + split heads
    ln_phi_kernel<<<Bb*Nn, 512>>>(qw, qb, kw, kb);
    // 3) compressed keys
    kcmp_kernel<<<BHc*NBc, 64>>>();
    // 4) kv / z
    {
        dim3 grid(BHc, NCHUNK);
        kv_chunk_kernel<<<grid, 256>>>();
        int total = BHc*Dd*Dd + BHc*Dd;
        kv_reduce_kernel<<<(total + 255)/256, 256>>>();
    }
    // 5) router + topk
    router_topk_kernel<<<BHc*(Nn/64), 256>>>();
    // 6) sparse + linear attention
    attn_kernel<<<BHc*(Nn/8), 256>>>();
    // 7) out = attn @ w_proj + b_proj
    {
        dim3 grid(Cc/GBN, Bb*Nn/GBM);
        gemm_tf32_kernel<<<grid, 256>>>((const float*)p_attn, w_proj, b_proj,
                                        out, Bb*Nn, Cc, Cc);
    }
    (void)in_sizes; (void)n_in; (void)out_size;
}